// round 12
// baseline (speedup 1.0000x reference)
#include <cuda_runtime.h>
#include <cuda_bf16.h>
#include <cstdint>

// Problem constants (fixed by dataset): B=2, C=256, N=4096
#define NB 2
#define NC 256
#define NP 4096
#define ISPLIT 256          // i-splits for K^T a (16 rows per block)

#define INV255 (1.0f / 255.0f)

// ---------------- scratch (static device globals; no allocations) ----------
__device__ uint8_t g_K[(size_t)NB * NP * NP];             // 32 MB affinity kernel, u8 fixed-point
__device__ __nv_bfloat16 g_f1b[(size_t)NB * NC * NP];     // 4 MB normalized bf16 feats
__device__ __nv_bfloat16 g_f2b[(size_t)NB * NC * NP];
__device__ float g_a[NB * NP];
__device__ float g_b[NB * NP];
__device__ float g_part[(size_t)ISPLIT * NB * NP];        // 8 MB KTa partials (raw, x255)
__device__ float g_invn1[NB * NP], g_invn2[NB * NP];
__device__ float g_sq1[NB * NP], g_sq2[NB * NP];
__device__ float g_eps, g_power;

// ---- u8 -> float decode: PRMT byte into 2^23 mantissa, exact subtract ------
// returns {q0,q1,q2,q3} as floats in [0,255] (exact)
__device__ __forceinline__ float4 q2f(uint32_t w) {
    uint32_t r0, r1, r2, r3;
    const uint32_t hi = 0x4Bu;      // byte4 = 0x4B, bytes 5..7 = 0
    asm("prmt.b32 %0, %1, %2, 0x4550;" : "=r"(r0) : "r"(w), "r"(hi));
    asm("prmt.b32 %0, %1, %2, 0x4551;" : "=r"(r1) : "r"(w), "r"(hi));
    asm("prmt.b32 %0, %1, %2, 0x4552;" : "=r"(r2) : "r"(w), "r"(hi));
    asm("prmt.b32 %0, %1, %2, 0x4553;" : "=r"(r3) : "r"(w), "r"(hi));
    float4 f;
    f.x = __uint_as_float(r0) - 8388608.0f;
    f.y = __uint_as_float(r1) - 8388608.0f;
    f.z = __uint_as_float(r2) - 8388608.0f;
    f.w = __uint_as_float(r3) - 8388608.0f;
    return f;
}

// ---------------- scalar prep ----------------------------------------------
__global__ void fm_prep(const float* __restrict__ gamma, const float* __restrict__ epsilon) {
    if (threadIdx.x == 0) {
        float eps = expf(epsilon[0]) + 0.03f;
        float gam = expf(gamma[0]) + 0.03f;
        g_eps = eps;
        g_power = gam / (gam + eps);
    }
}

// ---------------- per-point prep: feature inv-norms, |p|^2, a0 -------------
__global__ void fm_point_prep(const float* __restrict__ pc1, const float* __restrict__ pc2,
                              const float* __restrict__ f1, const float* __restrict__ f2) {
    int p = blockIdx.x * blockDim.x + threadIdx.x;     // 0 .. NB*NP-1
    if (p >= NB * NP) return;
    int b = p >> 12;
    int n = p & (NP - 1);
    const float* F1 = f1 + (size_t)b * NC * NP + n;
    const float* F2 = f2 + (size_t)b * NC * NP + n;
    float s1 = 0.f, s2 = 0.f;
#pragma unroll 8
    for (int c = 0; c < NC; c++) {
        float v = F1[(size_t)c * NP]; s1 += v * v;
        float w = F2[(size_t)c * NP]; s2 += w * w;
    }
    g_invn1[p] = 1.0f / sqrtf(s1 + 1e-6f);
    g_invn2[p] = 1.0f / sqrtf(s2 + 1e-6f);
    const float* P1 = pc1 + (size_t)b * 3 * NP + n;
    const float* P2 = pc2 + (size_t)b * 3 * NP + n;
    float q1 = 0.f, q2 = 0.f;
#pragma unroll
    for (int d = 0; d < 3; d++) {
        float v = P1[(size_t)d * NP]; q1 += v * v;
        float w = P2[(size_t)d * NP]; q2 += w * w;
    }
    g_sq1[p] = q1;
    g_sq2[p] = q2;
    g_a[p]   = 1.0f / NP;
}

// ---------------- normalize + convert features to bf16 [B,C,N] -------------
__global__ void fm_convert(const float* __restrict__ f1, const float* __restrict__ f2) {
    int idx = blockIdx.x * blockDim.x + threadIdx.x;   // per 8 elements
    const int total8 = NB * NC * NP / 8;
    if (idx >= total8) return;
    int e0 = idx * 8;
    int b = e0 / (NC * NP);
    int n = e0 & (NP - 1);
    const float* inv1 = g_invn1 + b * NP + n;
    const float* inv2 = g_invn2 + b * NP + n;
    float4 w0 = *(const float4*)inv1, w1 = *(const float4*)(inv1 + 4);
    float4 u0 = *(const float4*)inv2, u1 = *(const float4*)(inv2 + 4);
    float4 v0 = *(const float4*)(f1 + e0), v1 = *(const float4*)(f1 + e0 + 4);
    float4 x0 = *(const float4*)(f2 + e0), x1 = *(const float4*)(f2 + e0 + 4);
    __nv_bfloat16 o1[8], o2[8];
    o1[0] = __float2bfloat16(v0.x * w0.x); o1[1] = __float2bfloat16(v0.y * w0.y);
    o1[2] = __float2bfloat16(v0.z * w0.z); o1[3] = __float2bfloat16(v0.w * w0.w);
    o1[4] = __float2bfloat16(v1.x * w1.x); o1[5] = __float2bfloat16(v1.y * w1.y);
    o1[6] = __float2bfloat16(v1.z * w1.z); o1[7] = __float2bfloat16(v1.w * w1.w);
    o2[0] = __float2bfloat16(x0.x * u0.x); o2[1] = __float2bfloat16(x0.y * u0.y);
    o2[2] = __float2bfloat16(x0.z * u0.z); o2[3] = __float2bfloat16(x0.w * u0.w);
    o2[4] = __float2bfloat16(x1.x * u1.x); o2[5] = __float2bfloat16(x1.y * u1.y);
    o2[6] = __float2bfloat16(x1.z * u1.z); o2[7] = __float2bfloat16(x1.w * u1.w);
    *(uint4*)(g_f1b + e0) = *(uint4*)o1;
    *(uint4*)(g_f2b + e0) = *(uint4*)o2;
}

// ---------------- K build: HMMA bf16 GEMM + support/exp + u8 quantize ------
#define KSTRIDE 136
__global__ __launch_bounds__(256)
void fm_build_k(const float* __restrict__ pc1, const float* __restrict__ pc2) {
    __shared__ __nv_bfloat16 As[64][KSTRIDE];
    __shared__ __nv_bfloat16 Bs[64][KSTRIDE];
    __shared__ float sSq1[128], sSq2[128];
    __shared__ float sP1[3][128], sP2[3][128];

    int b  = blockIdx.z;
    int i0 = blockIdx.y * 128;
    int j0 = blockIdx.x * 128;
    int tid  = threadIdx.x;
    int warp = tid >> 5, lane = tid & 31;
    int wm = warp >> 2, wn = warp & 3;          // 2 x 4 warp grid

    if (tid < 128) {
        int i = i0 + tid;
        sSq1[tid] = g_sq1[b * NP + i];
#pragma unroll
        for (int d = 0; d < 3; d++)
            sP1[d][tid] = pc1[((size_t)b * 3 + d) * NP + i];
    } else {
        int t = tid - 128;
        int j = j0 + t;
        sSq2[t] = g_sq2[b * NP + j];
#pragma unroll
        for (int d = 0; d < 3; d++)
            sP2[d][t] = pc2[((size_t)b * 3 + d) * NP + j];
    }

    const __nv_bfloat16* F1 = g_f1b + (size_t)b * NC * NP;
    const __nv_bfloat16* F2 = g_f2b + (size_t)b * NC * NP;

    float acc[4][4][4];
#pragma unroll
    for (int fm = 0; fm < 4; fm++)
#pragma unroll
        for (int nb = 0; nb < 4; nb++)
#pragma unroll
            for (int e = 0; e < 4; e++) acc[fm][nb][e] = 0.f;

    int kA = ((lane >= 16) ? 8 : 0) + (lane & 7);   // A: k offset
    int mA = ((lane >> 3) & 1) * 8;                 // A: m offset
    int kB = (((lane >> 3) & 1) * 8) + (lane & 7);  // B: k offset
    int nB = (lane >= 16) ? 8 : 0;                  // B: n offset

    for (int c0 = 0; c0 < NC; c0 += 64) {
        __syncthreads();
#pragma unroll
        for (int s = 0; s < 4; s++) {
            int idx = tid + s * 256;
            int kk  = idx >> 4;
            int col = (idx & 15) * 8;
            *(uint4*)&As[kk][col] = *(const uint4*)&F1[(size_t)(c0 + kk) * NP + i0 + col];
            *(uint4*)&Bs[kk][col] = *(const uint4*)&F2[(size_t)(c0 + kk) * NP + j0 + col];
        }
        __syncthreads();
#pragma unroll
        for (int ks = 0; ks < 4; ks++) {
            int kb = ks * 16;
            uint32_t a[4][4];
#pragma unroll
            for (int fm = 0; fm < 4; fm++) {
                uint32_t saddr = (uint32_t)__cvta_generic_to_shared(
                    &As[kb + kA][wm * 64 + fm * 16 + mA]);
                asm volatile("ldmatrix.sync.aligned.m8n8.x4.trans.shared.b16 "
                             "{%0,%1,%2,%3}, [%4];"
                             : "=r"(a[fm][0]), "=r"(a[fm][1]), "=r"(a[fm][2]), "=r"(a[fm][3])
                             : "r"(saddr));
            }
            uint32_t bb[2][4];
#pragma unroll
            for (int fn = 0; fn < 2; fn++) {
                uint32_t saddr = (uint32_t)__cvta_generic_to_shared(
                    &Bs[kb + kB][wn * 32 + fn * 16 + nB]);
                asm volatile("ldmatrix.sync.aligned.m8n8.x4.trans.shared.b16 "
                             "{%0,%1,%2,%3}, [%4];"
                             : "=r"(bb[fn][0]), "=r"(bb[fn][1]), "=r"(bb[fn][2]), "=r"(bb[fn][3])
                             : "r"(saddr));
            }
#pragma unroll
            for (int fm = 0; fm < 4; fm++) {
#pragma unroll
                for (int nb = 0; nb < 4; nb++) {
                    int fn = nb >> 1, h = nb & 1;
                    asm volatile(
                        "mma.sync.aligned.m16n8k16.row.col.f32.bf16.bf16.f32 "
                        "{%0,%1,%2,%3}, {%4,%5,%6,%7}, {%8,%9}, {%0,%1,%2,%3};"
                        : "+f"(acc[fm][nb][0]), "+f"(acc[fm][nb][1]),
                          "+f"(acc[fm][nb][2]), "+f"(acc[fm][nb][3])
                        : "r"(a[fm][0]), "r"(a[fm][1]), "r"(a[fm][2]), "r"(a[fm][3]),
                          "r"(bb[fn][h * 2]), "r"(bb[fn][h * 2 + 1]));
                }
            }
        }
    }

    float einv = 1.0f / g_eps;
    int g  = lane >> 2;
    int t2 = (lane & 3) * 2;
    uint8_t* Kout = g_K + (size_t)b * NP * NP;
#pragma unroll
    for (int fm = 0; fm < 4; fm++) {
#pragma unroll
        for (int h = 0; h < 2; h++) {
            int ii = wm * 64 + fm * 16 + g + h * 8;
            float sq1 = sSq1[ii];
            float p1x = sP1[0][ii], p1y = sP1[1][ii], p1z = sP1[2][ii];
#pragma unroll
            for (int nb = 0; nb < 4; nb++) {
                int jj = wn * 32 + nb * 8 + t2;
                float c0 = acc[fm][nb][h * 2 + 0];
                float c1 = acc[fm][nb][h * 2 + 1];
                float d0 = sq1 + sSq2[jj]
                         - 2.0f * (p1x * sP2[0][jj] + p1y * sP2[1][jj] + p1z * sP2[2][jj]);
                float d1 = sq1 + sSq2[jj + 1]
                         - 2.0f * (p1x * sP2[0][jj + 1] + p1y * sP2[1][jj + 1] + p1z * sP2[2][jj + 1]);
                float k0 = (d0 < 0.25f) ? __expf((c0 - 1.0f) * einv) : 0.0f;
                float k1 = (d1 < 0.25f) ? __expf((c1 - 1.0f) * einv) : 0.0f;
                uchar2 qv;
                qv.x = (uint8_t)__float2uint_rn(fminf(k0 * 255.0f, 255.0f));
                qv.y = (uint8_t)__float2uint_rn(fminf(k1 * 255.0f, 255.0f));
                *(uchar2*)&Kout[(size_t)(i0 + ii) * NP + j0 + jj] = qv;
            }
        }
    }
}

// ---------------- KTa partials (column sweep, u8) --------------------------
// grid (ISPLIT=256, NB), 256 threads. Block: 16 rows x full 4096 cols;
// thread owns 16 consecutive cols (one uint4 = 16 u8 per row).
// Partials are RAW (x255); b_update applies 1/255.
__global__ __launch_bounds__(256)
void fm_kta(void) {
    int b  = blockIdx.y;
    int i0 = blockIdx.x * (NP / ISPLIT);            // 16 rows per block
    const uint8_t* Kp = g_K + (size_t)b * NP * NP;
    const float* ap = g_a + b * NP;
    int j0 = threadIdx.x * 16;

    float acc[16];
#pragma unroll
    for (int k = 0; k < 16; k++) acc[k] = 0.f;

#pragma unroll 4
    for (int i = 0; i < NP / ISPLIT; i++) {
        uint4 kv = __ldg((const uint4*)(Kp + (size_t)(i0 + i) * NP + j0));
        float av = __ldg(&ap[i0 + i]);
        float4 f0 = q2f(kv.x), f1 = q2f(kv.y), f2 = q2f(kv.z), f3 = q2f(kv.w);
        acc[0]  = fmaf(f0.x, av, acc[0]);  acc[1]  = fmaf(f0.y, av, acc[1]);
        acc[2]  = fmaf(f0.z, av, acc[2]);  acc[3]  = fmaf(f0.w, av, acc[3]);
        acc[4]  = fmaf(f1.x, av, acc[4]);  acc[5]  = fmaf(f1.y, av, acc[5]);
        acc[6]  = fmaf(f1.z, av, acc[6]);  acc[7]  = fmaf(f1.w, av, acc[7]);
        acc[8]  = fmaf(f2.x, av, acc[8]);  acc[9]  = fmaf(f2.y, av, acc[9]);
        acc[10] = fmaf(f2.z, av, acc[10]); acc[11] = fmaf(f2.w, av, acc[11]);
        acc[12] = fmaf(f3.x, av, acc[12]); acc[13] = fmaf(f3.y, av, acc[13]);
        acc[14] = fmaf(f3.z, av, acc[14]); acc[15] = fmaf(f3.w, av, acc[15]);
    }

    float* dst = &g_part[(size_t)blockIdx.x * (NB * NP) + b * NP + j0];
#pragma unroll
    for (int q = 0; q < 4; q++)
        *(float4*)(dst + q * 4) = make_float4(acc[q * 4 + 0], acc[q * 4 + 1],
                                              acc[q * 4 + 2], acc[q * 4 + 3]);
}

// ---------------- b = (prob2/(KTa + 1e-8))^power  (applies 1/255) ----------
__global__ __launch_bounds__(256)
void fm_b_update(void) {
    int t = blockIdx.x * blockDim.x + threadIdx.x;   // 0 .. 4*NB*NP-1
    int p = t >> 2;
    int q = t & 3;
    if (p >= NB * NP) return;
    float s = 0.f;
#pragma unroll
    for (int i = 0; i < ISPLIT / 4; i++) {
        int k = q * (ISPLIT / 4) + i;
        s += g_part[(size_t)k * (NB * NP) + p];
    }
    s += __shfl_xor_sync(0xffffffffu, s, 1);
    s += __shfl_xor_sync(0xffffffffu, s, 2);
    if (q == 0)
        g_b[p] = __powf((1.0f / NP) / (s * INV255 + 1e-8f), g_power);
}

// ---------------- Kb (row sweep, u8) fused with a-update -------------------
__global__ __launch_bounds__(256)
void fm_kb_a(void) {
    int warp = (blockIdx.x * blockDim.x + threadIdx.x) >> 5;
    int lane = threadIdx.x & 31;
    if (warp >= NB * NP) return;
    int b = warp >> 12, i = warp & (NP - 1);
    const uint8_t* Krow = g_K + (size_t)b * NP * NP + (size_t)i * NP;
    const float* bp = g_b + b * NP;
    float acc = 0.f;
#pragma unroll
    for (int it = 0; it < NP / 512; it++) {           // 8 iters, 16 elems each
        int j = it * 512 + lane * 16;
        uint4 kv = __ldg((const uint4*)(Krow + j));
        float4 f0 = q2f(kv.x), f1 = q2f(kv.y), f2 = q2f(kv.z), f3 = q2f(kv.w);
        float4 b0 = *(const float4*)(bp + j);
        float4 b1 = *(const float4*)(bp + j + 4);
        float4 b2 = *(const float4*)(bp + j + 8);
        float4 b3 = *(const float4*)(bp + j + 12);
        acc += f0.x * b0.x + f0.y * b0.y + f0.z * b0.z + f0.w * b0.w
             + f1.x * b1.x + f1.y * b1.y + f1.z * b1.z + f1.w * b1.w
             + f2.x * b2.x + f2.y * b2.y + f2.z * b2.z + f2.w * b2.w
             + f3.x * b3.x + f3.y * b3.y + f3.z * b3.z + f3.w * b3.w;
    }
#pragma unroll
    for (int o = 16; o; o >>= 1) acc += __shfl_xor_sync(0xffffffffu, acc, o);
    if (lane == 0)
        g_a[warp] = __powf((1.0f / NP) / (acc * INV255 + 1e-8f), g_power);
}

// ---------------- last iteration: Kb + a-update + flow, one K pass ---------
__global__ __launch_bounds__(256)
void fm_kb_flow(const float* __restrict__ pc1, const float* __restrict__ pc2,
                float* __restrict__ out) {
    int warp = (blockIdx.x * blockDim.x + threadIdx.x) >> 5;
    int lane = threadIdx.x & 31;
    if (warp >= NB * NP) return;
    int b = warp >> 12, i = warp & (NP - 1);
    const uint8_t* Krow = g_K + (size_t)b * NP * NP + (size_t)i * NP;
    const float* bp  = g_b + b * NP;
    const float* p2x = pc2 + (size_t)b * 3 * NP;
    const float* p2y = p2x + NP;
    const float* p2z = p2y + NP;
    float s = 0.f, vx = 0.f, vy = 0.f, vz = 0.f;
#pragma unroll
    for (int it = 0; it < NP / 512; it++) {
        int j = it * 512 + lane * 16;
        uint4 kv = __ldg((const uint4*)(Krow + j));
        float4 f[4] = { q2f(kv.x), q2f(kv.y), q2f(kv.z), q2f(kv.w) };
#pragma unroll
        for (int q = 0; q < 4; q++) {
            float4 bq = *(const float4*)(bp + j + q * 4);
            float4 xq = *(const float4*)(p2x + j + q * 4);
            float4 yq = *(const float4*)(p2y + j + q * 4);
            float4 zq = *(const float4*)(p2z + j + q * 4);
            float t0 = f[q].x * bq.x, t1 = f[q].y * bq.y;
            float t2 = f[q].z * bq.z, t3 = f[q].w * bq.w;
            s  += t0 + t1 + t2 + t3;
            vx += t0 * xq.x + t1 * xq.y + t2 * xq.z + t3 * xq.w;
            vy += t0 * yq.x + t1 * yq.y + t2 * yq.z + t3 * yq.w;
            vz += t0 * zq.x + t1 * zq.y + t2 * zq.z + t3 * zq.w;
        }
    }
#pragma unroll
    for (int o = 16; o; o >>= 1) {
        s  += __shfl_xor_sync(0xffffffffu, s,  o);
        vx += __shfl_xor_sync(0xffffffffu, vx, o);
        vy += __shfl_xor_sync(0xffffffffu, vy, o);
        vz += __shfl_xor_sync(0xffffffffu, vz, o);
    }
    if (lane == 0) {
        s  *= INV255; vx *= INV255; vy *= INV255; vz *= INV255;
        float a = __powf((1.0f / NP) / (s + 1e-8f), g_power);   // final a-update
        float rden = 1.0f / (a * s + 1e-6f);
        const float* P1 = pc1 + (size_t)b * 3 * NP + i;
        out[warp * 3 + 0] = a * vx * rden - P1[0 * NP];
        out[warp * 3 + 1] = a * vy * rden - P1[1 * NP];
        out[warp * 3 + 2] = a * vz * rden - P1[2 * NP];
    }
}

// ---------------- launch ----------------------------------------------------
extern "C" void kernel_launch(void* const* d_in, const int* in_sizes, int n_in,
                              void* d_out, int out_size) {
    const float* pc1   = (const float*)d_in[0];
    const float* pc2   = (const float*)d_in[1];
    const float* f1    = (const float*)d_in[2];
    const float* f2    = (const float*)d_in[3];
    const float* gamma = (const float*)d_in[4];
    const float* eps   = (const float*)d_in[5];
    float* out = (float*)d_out;

    fm_prep<<<1, 32>>>(gamma, eps);
    fm_point_prep<<<(NB * NP + 255) / 256, 256>>>(pc1, pc2, f1, f2);
    fm_convert<<<(NB * NC * NP / 8 + 255) / 256, 256>>>(f1, f2);
    fm_build_k<<<dim3(NP / 128, NP / 128, NB), 256>>>(pc1, pc2);

    for (int it = 0; it < 9; it++) {
        fm_kta<<<dim3(ISPLIT, NB), 256>>>();
        fm_b_update<<<(4 * NB * NP + 255) / 256, 256>>>();
        fm_kb_a<<<NB * NP / 8, 256>>>();
    }
    fm_kta<<<dim3(ISPLIT, NB), 256>>>();
    fm_b_update<<<(4 * NB * NP + 255) / 256, 256>>>();
    fm_kb_flow<<<NB * NP / 8, 256>>>(pc1, pc2, out);
}

// round 13
// speedup vs baseline: 1.2346x; 1.2346x over previous
#include <cuda_runtime.h>
#include <cuda_bf16.h>
#include <cstdint>

// Problem constants (fixed by dataset): B=2, C=256, N=4096
#define NB 2
#define NC 256
#define NP 4096
#define ISPLIT 128          // i-splits for the K^T a column sweep

// ---------------- scratch (static device globals; no allocations) ----------
__device__ __nv_bfloat16 g_K[(size_t)NB * NP * NP];       // 64 MB affinity kernel, bf16
__device__ __nv_bfloat16 g_f1b[(size_t)NB * NC * NP];     // 4 MB normalized bf16 feats
__device__ __nv_bfloat16 g_f2b[(size_t)NB * NC * NP];
__device__ float g_a[NB * NP];
__device__ float g_b[NB * NP];
__device__ float g_part[(size_t)ISPLIT * NB * NP];        // 4 MB KTa partials
__device__ float g_invn1[NB * NP], g_invn2[NB * NP];
__device__ float g_sq1[NB * NP], g_sq2[NB * NP];
__device__ float g_eps, g_power;

// ---------------- scalar prep ----------------------------------------------
__global__ void fm_prep(const float* __restrict__ gamma, const float* __restrict__ epsilon) {
    if (threadIdx.x == 0) {
        float eps = expf(epsilon[0]) + 0.03f;
        float gam = expf(gamma[0]) + 0.03f;
        g_eps = eps;
        g_power = gam / (gam + eps);
    }
}

// ---------------- per-point prep: feature inv-norms, |p|^2, a0 -------------
__global__ void fm_point_prep(const float* __restrict__ pc1, const float* __restrict__ pc2,
                              const float* __restrict__ f1, const float* __restrict__ f2) {
    int p = blockIdx.x * blockDim.x + threadIdx.x;     // 0 .. NB*NP-1
    if (p >= NB * NP) return;
    int b = p >> 12;
    int n = p & (NP - 1);
    const float* F1 = f1 + (size_t)b * NC * NP + n;
    const float* F2 = f2 + (size_t)b * NC * NP + n;
    float s1 = 0.f, s2 = 0.f;
#pragma unroll 8
    for (int c = 0; c < NC; c++) {
        float v = F1[(size_t)c * NP]; s1 += v * v;
        float w = F2[(size_t)c * NP]; s2 += w * w;
    }
    g_invn1[p] = 1.0f / sqrtf(s1 + 1e-6f);
    g_invn2[p] = 1.0f / sqrtf(s2 + 1e-6f);
    const float* P1 = pc1 + (size_t)b * 3 * NP + n;
    const float* P2 = pc2 + (size_t)b * 3 * NP + n;
    float q1 = 0.f, q2 = 0.f;
#pragma unroll
    for (int d = 0; d < 3; d++) {
        float v = P1[(size_t)d * NP]; q1 += v * v;
        float w = P2[(size_t)d * NP]; q2 += w * w;
    }
    g_sq1[p] = q1;
    g_sq2[p] = q2;
    g_a[p]   = 1.0f / NP;
}

// ---------------- normalize + convert features to bf16 [B,C,N] -------------
__global__ void fm_convert(const float* __restrict__ f1, const float* __restrict__ f2) {
    int idx = blockIdx.x * blockDim.x + threadIdx.x;   // per 8 elements
    const int total8 = NB * NC * NP / 8;
    if (idx >= total8) return;
    int e0 = idx * 8;
    int b = e0 / (NC * NP);
    int n = e0 & (NP - 1);
    const float* inv1 = g_invn1 + b * NP + n;
    const float* inv2 = g_invn2 + b * NP + n;
    float4 w0 = *(const float4*)inv1, w1 = *(const float4*)(inv1 + 4);
    float4 u0 = *(const float4*)inv2, u1 = *(const float4*)(inv2 + 4);
    float4 v0 = *(const float4*)(f1 + e0), v1 = *(const float4*)(f1 + e0 + 4);
    float4 x0 = *(const float4*)(f2 + e0), x1 = *(const float4*)(f2 + e0 + 4);
    __nv_bfloat16 o1[8], o2[8];
    o1[0] = __float2bfloat16(v0.x * w0.x); o1[1] = __float2bfloat16(v0.y * w0.y);
    o1[2] = __float2bfloat16(v0.z * w0.z); o1[3] = __float2bfloat16(v0.w * w0.w);
    o1[4] = __float2bfloat16(v1.x * w1.x); o1[5] = __float2bfloat16(v1.y * w1.y);
    o1[6] = __float2bfloat16(v1.z * w1.z); o1[7] = __float2bfloat16(v1.w * w1.w);
    o2[0] = __float2bfloat16(x0.x * u0.x); o2[1] = __float2bfloat16(x0.y * u0.y);
    o2[2] = __float2bfloat16(x0.z * u0.z); o2[3] = __float2bfloat16(x0.w * u0.w);
    o2[4] = __float2bfloat16(x1.x * u1.x); o2[5] = __float2bfloat16(x1.y * u1.y);
    o2[6] = __float2bfloat16(x1.z * u1.z); o2[7] = __float2bfloat16(x1.w * u1.w);
    *(uint4*)(g_f1b + e0) = *(uint4*)o1;
    *(uint4*)(g_f2b + e0) = *(uint4*)o2;
}

// ---------------- K build: HMMA bf16 GEMM, cp.async double-buffered --------
// 128x128 block tile, 8 warps (2m x 4n), warp tile 64x32.
// K-chunks of 32 double-buffered via cp.async (LDGSTS): loads of chunk c+1
// stream while HMMAs consume chunk c. Same 39 KB smem as the sync version.
#define KSTRIDE 136
__global__ __launch_bounds__(256)
void fm_build_k(const float* __restrict__ pc1, const float* __restrict__ pc2) {
    __shared__ __nv_bfloat16 As[2][32][KSTRIDE];
    __shared__ __nv_bfloat16 Bs[2][32][KSTRIDE];
    __shared__ float sSq1[128], sSq2[128];
    __shared__ float sP1[3][128], sP2[3][128];

    int b  = blockIdx.z;
    int i0 = blockIdx.y * 128;
    int j0 = blockIdx.x * 128;
    int tid  = threadIdx.x;
    int warp = tid >> 5, lane = tid & 31;
    int wm = warp >> 2, wn = warp & 3;          // 2 x 4 warp grid

    if (tid < 128) {
        int i = i0 + tid;
        sSq1[tid] = g_sq1[b * NP + i];
#pragma unroll
        for (int d = 0; d < 3; d++)
            sP1[d][tid] = pc1[((size_t)b * 3 + d) * NP + i];
    } else {
        int t = tid - 128;
        int j = j0 + t;
        sSq2[t] = g_sq2[b * NP + j];
#pragma unroll
        for (int d = 0; d < 3; d++)
            sP2[d][t] = pc2[((size_t)b * 3 + d) * NP + j];
    }

    const __nv_bfloat16* F1 = g_f1b + (size_t)b * NC * NP;
    const __nv_bfloat16* F2 = g_f2b + (size_t)b * NC * NP;

    // async-load one 32-K chunk (A: 32x128, B: 32x128) into buffer buf
    auto load_chunk = [&](int c, int buf) {
#pragma unroll
        for (int k = 0; k < 2; k++) {
            int idx = tid + k * 256;             // 0..511
            int row = idx >> 4;                  // 16 uint4 per 128-col row
            int col = (idx & 15) * 8;
            uint32_t dA = (uint32_t)__cvta_generic_to_shared(&As[buf][row][col]);
            uint32_t dB = (uint32_t)__cvta_generic_to_shared(&Bs[buf][row][col]);
            const __nv_bfloat16* sA = F1 + (size_t)(c * 32 + row) * NP + i0 + col;
            const __nv_bfloat16* sB = F2 + (size_t)(c * 32 + row) * NP + j0 + col;
            asm volatile("cp.async.cg.shared.global [%0], [%1], 16;" :: "r"(dA), "l"(sA));
            asm volatile("cp.async.cg.shared.global [%0], [%1], 16;" :: "r"(dB), "l"(sB));
        }
        asm volatile("cp.async.commit_group;");
    };

    float acc[4][4][4];
#pragma unroll
    for (int fm = 0; fm < 4; fm++)
#pragma unroll
        for (int nb = 0; nb < 4; nb++)
#pragma unroll
            for (int e = 0; e < 4; e++) acc[fm][nb][e] = 0.f;

    int kA = ((lane >= 16) ? 8 : 0) + (lane & 7);   // A: k offset
    int mA = ((lane >> 3) & 1) * 8;                 // A: m offset
    int kB = (((lane >> 3) & 1) * 8) + (lane & 7);  // B: k offset
    int nB = (lane >= 16) ? 8 : 0;                  // B: n offset

    load_chunk(0, 0);

    const int NCHUNK = NC / 32;                      // 8
    for (int c = 0; c < NCHUNK; c++) {
        int buf = c & 1;
        if (c + 1 < NCHUNK) {
            load_chunk(c + 1, buf ^ 1);
            asm volatile("cp.async.wait_group 1;");  // chunk c landed
        } else {
            asm volatile("cp.async.wait_group 0;");
        }
        __syncthreads();
#pragma unroll
        for (int ks = 0; ks < 2; ks++) {
            int kb = ks * 16;
            uint32_t a[4][4];
#pragma unroll
            for (int fm = 0; fm < 4; fm++) {
                uint32_t saddr = (uint32_t)__cvta_generic_to_shared(
                    &As[buf][kb + kA][wm * 64 + fm * 16 + mA]);
                asm volatile("ldmatrix.sync.aligned.m8n8.x4.trans.shared.b16 "
                             "{%0,%1,%2,%3}, [%4];"
                             : "=r"(a[fm][0]), "=r"(a[fm][1]), "=r"(a[fm][2]), "=r"(a[fm][3])
                             : "r"(saddr));
            }
            uint32_t bb[2][4];
#pragma unroll
            for (int fn = 0; fn < 2; fn++) {
                uint32_t saddr = (uint32_t)__cvta_generic_to_shared(
                    &Bs[buf][kb + kB][wn * 32 + fn * 16 + nB]);
                asm volatile("ldmatrix.sync.aligned.m8n8.x4.trans.shared.b16 "
                             "{%0,%1,%2,%3}, [%4];"
                             : "=r"(bb[fn][0]), "=r"(bb[fn][1]), "=r"(bb[fn][2]), "=r"(bb[fn][3])
                             : "r"(saddr));
            }
#pragma unroll
            for (int fm = 0; fm < 4; fm++) {
#pragma unroll
                for (int nb = 0; nb < 4; nb++) {
                    int fn = nb >> 1, h = nb & 1;
                    asm volatile(
                        "mma.sync.aligned.m16n8k16.row.col.f32.bf16.bf16.f32 "
                        "{%0,%1,%2,%3}, {%4,%5,%6,%7}, {%8,%9}, {%0,%1,%2,%3};"
                        : "+f"(acc[fm][nb][0]), "+f"(acc[fm][nb][1]),
                          "+f"(acc[fm][nb][2]), "+f"(acc[fm][nb][3])
                        : "r"(a[fm][0]), "r"(a[fm][1]), "r"(a[fm][2]), "r"(a[fm][3]),
                          "r"(bb[fn][h * 2]), "r"(bb[fn][h * 2 + 1]));
                }
            }
        }
        __syncthreads();   // all reads of buf done before it is refilled
    }

    // epilogue: dist/support + exp, write bf16 pairs
    float einv = 1.0f / g_eps;
    int g  = lane >> 2;
    int t2 = (lane & 3) * 2;
    __nv_bfloat16* Kout = g_K + (size_t)b * NP * NP;
#pragma unroll
    for (int fm = 0; fm < 4; fm++) {
#pragma unroll
        for (int h = 0; h < 2; h++) {
            int ii = wm * 64 + fm * 16 + g + h * 8;
            float sq1 = sSq1[ii];
            float p1x = sP1[0][ii], p1y = sP1[1][ii], p1z = sP1[2][ii];
#pragma unroll
            for (int nb = 0; nb < 4; nb++) {
                int jj = wn * 32 + nb * 8 + t2;
                float c0 = acc[fm][nb][h * 2 + 0];
                float c1 = acc[fm][nb][h * 2 + 1];
                float d0 = sq1 + sSq2[jj]
                         - 2.0f * (p1x * sP2[0][jj] + p1y * sP2[1][jj] + p1z * sP2[2][jj]);
                float d1 = sq1 + sSq2[jj + 1]
                         - 2.0f * (p1x * sP2[0][jj + 1] + p1y * sP2[1][jj + 1] + p1z * sP2[2][jj + 1]);
                float k0 = (d0 < 0.25f) ? __expf((c0 - 1.0f) * einv) : 0.0f;
                float k1 = (d1 < 0.25f) ? __expf((c1 - 1.0f) * einv) : 0.0f;
                __nv_bfloat162 kv;
                kv.x = __float2bfloat16(k0);
                kv.y = __float2bfloat16(k1);
                *(__nv_bfloat162*)&Kout[(size_t)(i0 + ii) * NP + j0 + jj] = kv;
            }
        }
    }
}

// ---------------- Sinkhorn: KTa partials (column sweep, vectorized) --------
__global__ __launch_bounds__(256)
void fm_kta(void) {
    int b  = blockIdx.z;
    int j  = blockIdx.x * 2048 + threadIdx.x * 8;
    int i0 = blockIdx.y * (NP / ISPLIT);            // 32 rows per block
    const __nv_bfloat16* Kp = g_K + (size_t)b * NP * NP;
    const float* ap = g_a + b * NP;

    float acc[8];
#pragma unroll
    for (int k = 0; k < 8; k++) acc[k] = 0.f;

#pragma unroll 8
    for (int i = i0; i < i0 + NP / ISPLIT; i++) {
        uint4 kv = __ldg((const uint4*)(Kp + (size_t)i * NP + j));
        float av = __ldg(&ap[i]);
        float2 f0 = __bfloat1622float2(*(__nv_bfloat162*)&kv.x);
        float2 f1 = __bfloat1622float2(*(__nv_bfloat162*)&kv.y);
        float2 f2 = __bfloat1622float2(*(__nv_bfloat162*)&kv.z);
        float2 f3 = __bfloat1622float2(*(__nv_bfloat162*)&kv.w);
        acc[0] += f0.x * av; acc[1] += f0.y * av;
        acc[2] += f1.x * av; acc[3] += f1.y * av;
        acc[4] += f2.x * av; acc[5] += f2.y * av;
        acc[6] += f3.x * av; acc[7] += f3.y * av;
    }

    float* dst = &g_part[(size_t)blockIdx.y * (NB * NP) + b * NP + j];
    *(float4*)(dst + 0) = make_float4(acc[0], acc[1], acc[2], acc[3]);
    *(float4*)(dst + 4) = make_float4(acc[4], acc[5], acc[6], acc[7]);
}

// ---------------- b = (prob2/(sum partials + 1e-8))^power ------------------
__global__ __launch_bounds__(256)
void fm_b_update(void) {
    int t = blockIdx.x * blockDim.x + threadIdx.x;   // 0 .. 4*NB*NP-1
    int p = t >> 2;
    int q = t & 3;
    if (p >= NB * NP) return;
    float s = 0.f;
#pragma unroll
    for (int i = 0; i < ISPLIT / 4; i++) {
        int k = q * (ISPLIT / 4) + i;
        s += g_part[(size_t)k * (NB * NP) + p];
    }
    s += __shfl_xor_sync(0xffffffffu, s, 1);
    s += __shfl_xor_sync(0xffffffffu, s, 2);
    if (q == 0)
        g_b[p] = __powf((1.0f / NP) / (s + 1e-8f), g_power);
}

// ---------------- Kb (row sweep, vectorized) fused with a-update -----------
__global__ __launch_bounds__(256)
void fm_kb_a(void) {
    int warp = (blockIdx.x * blockDim.x + threadIdx.x) >> 5;
    int lane = threadIdx.x & 31;
    if (warp >= NB * NP) return;
    int b = warp >> 12, i = warp & (NP - 1);
    const __nv_bfloat16* Krow = g_K + (size_t)b * NP * NP + (size_t)i * NP;
    const float* bp = g_b + b * NP;
    float acc = 0.f;
#pragma unroll
    for (int it = 0; it < NP / 256; it++) {           // 16 iters
        int j = it * 256 + lane * 8;
        uint4 kv = __ldg((const uint4*)(Krow + j));
        float4 b0 = *(const float4*)(bp + j);
        float4 b1 = *(const float4*)(bp + j + 4);
        float2 f0 = __bfloat1622float2(*(__nv_bfloat162*)&kv.x);
        float2 f1 = __bfloat1622float2(*(__nv_bfloat162*)&kv.y);
        float2 f2 = __bfloat1622float2(*(__nv_bfloat162*)&kv.z);
        float2 f3 = __bfloat1622float2(*(__nv_bfloat162*)&kv.w);
        acc += f0.x * b0.x + f0.y * b0.y + f1.x * b0.z + f1.y * b0.w
             + f2.x * b1.x + f2.y * b1.y + f3.x * b1.z + f3.y * b1.w;
    }
#pragma unroll
    for (int o = 16; o; o >>= 1) acc += __shfl_xor_sync(0xffffffffu, acc, o);
    if (lane == 0)
        g_a[warp] = __powf((1.0f / NP) / (acc + 1e-8f), g_power);
}

// ---------------- last iteration: Kb + a-update + flow, one K pass ---------
__global__ __launch_bounds__(256)
void fm_kb_flow(const float* __restrict__ pc1, const float* __restrict__ pc2,
                float* __restrict__ out) {
    int warp = (blockIdx.x * blockDim.x + threadIdx.x) >> 5;
    int lane = threadIdx.x & 31;
    if (warp >= NB * NP) return;
    int b = warp >> 12, i = warp & (NP - 1);
    const __nv_bfloat16* Krow = g_K + (size_t)b * NP * NP + (size_t)i * NP;
    const float* bp  = g_b + b * NP;
    const float* p2x = pc2 + (size_t)b * 3 * NP;
    const float* p2y = p2x + NP;
    const float* p2z = p2y + NP;
    float s = 0.f, vx = 0.f, vy = 0.f, vz = 0.f;
#pragma unroll
    for (int it = 0; it < NP / 256; it++) {
        int j = it * 256 + lane * 8;
        uint4 kv = __ldg((const uint4*)(Krow + j));
        float2 f0 = __bfloat1622float2(*(__nv_bfloat162*)&kv.x);
        float2 f1 = __bfloat1622float2(*(__nv_bfloat162*)&kv.y);
        float2 f2 = __bfloat1622float2(*(__nv_bfloat162*)&kv.z);
        float2 f3 = __bfloat1622float2(*(__nv_bfloat162*)&kv.w);
        float4 b0 = *(const float4*)(bp + j);
        float4 b1 = *(const float4*)(bp + j + 4);
        float t[8];
        t[0] = f0.x * b0.x; t[1] = f0.y * b0.y; t[2] = f1.x * b0.z; t[3] = f1.y * b0.w;
        t[4] = f2.x * b1.x; t[5] = f2.y * b1.y; t[6] = f3.x * b1.z; t[7] = f3.y * b1.w;
        float4 x0 = *(const float4*)(p2x + j), x1 = *(const float4*)(p2x + j + 4);
        float4 y0 = *(const float4*)(p2y + j), y1 = *(const float4*)(p2y + j + 4);
        float4 z0 = *(const float4*)(p2z + j), z1 = *(const float4*)(p2z + j + 4);
        s  += t[0] + t[1] + t[2] + t[3] + t[4] + t[5] + t[6] + t[7];
        vx += t[0] * x0.x + t[1] * x0.y + t[2] * x0.z + t[3] * x0.w
            + t[4] * x1.x + t[5] * x1.y + t[6] * x1.z + t[7] * x1.w;
        vy += t[0] * y0.x + t[1] * y0.y + t[2] * y0.z + t[3] * y0.w
            + t[4] * y1.x + t[5] * y1.y + t[6] * y1.z + t[7] * y1.w;
        vz += t[0] * z0.x + t[1] * z0.y + t[2] * z0.z + t[3] * z0.w
            + t[4] * z1.x + t[5] * z1.y + t[6] * z1.z + t[7] * z1.w;
    }
#pragma unroll
    for (int o = 16; o; o >>= 1) {
        s  += __shfl_xor_sync(0xffffffffu, s,  o);
        vx += __shfl_xor_sync(0xffffffffu, vx, o);
        vy += __shfl_xor_sync(0xffffffffu, vy, o);
        vz += __shfl_xor_sync(0xffffffffu, vz, o);
    }
    if (lane == 0) {
        float a = __powf((1.0f / NP) / (s + 1e-8f), g_power);   // final a-update
        float rden = 1.0f / (a * s + 1e-6f);
        const float* P1 = pc1 + (size_t)b * 3 * NP + i;
        out[warp * 3 + 0] = a * vx * rden - P1[0 * NP];
        out[warp * 3 + 1] = a * vy * rden - P1[1 * NP];
        out[warp * 3 + 2] = a * vz * rden - P1[2 * NP];
    }
}

// ---------------- launch ----------------------------------------------------
extern "C" void kernel_launch(void* const* d_in, const int* in_sizes, int n_in,
                              void* d_out, int out_size) {
    const float* pc1   = (const float*)d_in[0];
    const float* pc2   = (const float*)d_in[1];
    const float* f1    = (const float*)d_in[2];
    const float* f2    = (const float*)d_in[3];
    const float* gamma = (const float*)d_in[4];
    const float* eps   = (const float*)d_in[5];
    float* out = (float*)d_out;

    fm_prep<<<1, 32>>>(gamma, eps);
    fm_point_prep<<<(NB * NP + 255) / 256, 256>>>(pc1, pc2, f1, f2);
    fm_convert<<<(NB * NC * NP / 8 + 255) / 256, 256>>>(f1, f2);
    fm_build_k<<<dim3(NP / 128, NP / 128, NB), 256>>>(pc1, pc2);

    // iteration 1: b1 from uniform a0
    fm_kta<<<dim3(NP / 2048, ISPLIT, NB), 256>>>();
    fm_b_update<<<(4 * NB * NP + 255) / 256, 256>>>();
    // iterations 1..9 (a_t then b_{t+1})
    for (int it = 0; it < 9; it++) {
        fm_kb_a<<<NB * NP / 8, 256>>>();
        fm_kta<<<dim3(NP / 2048, ISPLIT, NB), 256>>>();
        fm_b_update<<<(4 * NB * NP + 255) / 256, 256>>>();
    }
    // iteration 10: a10 = f(K b10) computed inside flow, fused with transport
    fm_kb_flow<<<NB * NP / 8, 256>>>(pc1, pc2, out);
}

// round 15
// speedup vs baseline: 1.2928x; 1.0471x over previous
#include <cuda_runtime.h>
#include <cuda_bf16.h>
#include <cstdint>

// Problem constants (fixed by dataset): B=2, C=256, N=4096
#define NB 2
#define NC 256
#define NP 4096
#define ISPLIT 128          // i-splits for the K^T a column sweep

// ---------------- scratch (static device globals; no allocations) ----------
__device__ __nv_bfloat16 g_K[(size_t)NB * NP * NP];       // 64 MB affinity kernel, bf16
__device__ __nv_bfloat16 g_f1b[(size_t)NB * NC * NP];     // 4 MB normalized bf16 feats
__device__ __nv_bfloat16 g_f2b[(size_t)NB * NC * NP];
__device__ float g_a[NB * NP];
__device__ float g_b[NB * NP];
__device__ float g_part[(size_t)ISPLIT * NB * NP];        // 4 MB KTa partials
__device__ float g_invn1[NB * NP], g_invn2[NB * NP];
__device__ float g_sq1[NB * NP], g_sq2[NB * NP];
__device__ float g_eps, g_power;

// ---------------- scalar prep ----------------------------------------------
__global__ void fm_prep(const float* __restrict__ gamma, const float* __restrict__ epsilon) {
    if (threadIdx.x == 0) {
        float eps = expf(epsilon[0]) + 0.03f;
        float gam = expf(gamma[0]) + 0.03f;
        g_eps = eps;
        g_power = gam / (gam + eps);
    }
}

// ---------------- per-point prep: feature inv-norms, |p|^2, a0 -------------
__global__ void fm_point_prep(const float* __restrict__ pc1, const float* __restrict__ pc2,
                              const float* __restrict__ f1, const float* __restrict__ f2) {
    int p = blockIdx.x * blockDim.x + threadIdx.x;     // 0 .. NB*NP-1
    if (p >= NB * NP) return;
    int b = p >> 12;
    int n = p & (NP - 1);
    const float* F1 = f1 + (size_t)b * NC * NP + n;
    const float* F2 = f2 + (size_t)b * NC * NP + n;
    float s1 = 0.f, s2 = 0.f;
#pragma unroll 8
    for (int c = 0; c < NC; c++) {
        float v = F1[(size_t)c * NP]; s1 += v * v;
        float w = F2[(size_t)c * NP]; s2 += w * w;
    }
    g_invn1[p] = 1.0f / sqrtf(s1 + 1e-6f);
    g_invn2[p] = 1.0f / sqrtf(s2 + 1e-6f);
    const float* P1 = pc1 + (size_t)b * 3 * NP + n;
    const float* P2 = pc2 + (size_t)b * 3 * NP + n;
    float q1 = 0.f, q2 = 0.f;
#pragma unroll
    for (int d = 0; d < 3; d++) {
        float v = P1[(size_t)d * NP]; q1 += v * v;
        float w = P2[(size_t)d * NP]; q2 += w * w;
    }
    g_sq1[p] = q1;
    g_sq2[p] = q2;
    g_a[p]   = 1.0f / NP;
}

// ---------------- normalize + convert features to bf16 [B,C,N] -------------
__global__ void fm_convert(const float* __restrict__ f1, const float* __restrict__ f2) {
    int idx = blockIdx.x * blockDim.x + threadIdx.x;   // per 8 elements
    const int total8 = NB * NC * NP / 8;
    if (idx >= total8) return;
    int e0 = idx * 8;
    int b = e0 / (NC * NP);
    int n = e0 & (NP - 1);
    const float* inv1 = g_invn1 + b * NP + n;
    const float* inv2 = g_invn2 + b * NP + n;
    float4 w0 = *(const float4*)inv1, w1 = *(const float4*)(inv1 + 4);
    float4 u0 = *(const float4*)inv2, u1 = *(const float4*)(inv2 + 4);
    float4 v0 = *(const float4*)(f1 + e0), v1 = *(const float4*)(f1 + e0 + 4);
    float4 x0 = *(const float4*)(f2 + e0), x1 = *(const float4*)(f2 + e0 + 4);
    __nv_bfloat16 o1[8], o2[8];
    o1[0] = __float2bfloat16(v0.x * w0.x); o1[1] = __float2bfloat16(v0.y * w0.y);
    o1[2] = __float2bfloat16(v0.z * w0.z); o1[3] = __float2bfloat16(v0.w * w0.w);
    o1[4] = __float2bfloat16(v1.x * w1.x); o1[5] = __float2bfloat16(v1.y * w1.y);
    o1[6] = __float2bfloat16(v1.z * w1.z); o1[7] = __float2bfloat16(v1.w * w1.w);
    o2[0] = __float2bfloat16(x0.x * u0.x); o2[1] = __float2bfloat16(x0.y * u0.y);
    o2[2] = __float2bfloat16(x0.z * u0.z); o2[3] = __float2bfloat16(x0.w * u0.w);
    o2[4] = __float2bfloat16(x1.x * u1.x); o2[5] = __float2bfloat16(x1.y * u1.y);
    o2[6] = __float2bfloat16(x1.z * u1.z); o2[7] = __float2bfloat16(x1.w * u1.w);
    *(uint4*)(g_f1b + e0) = *(uint4*)o1;
    *(uint4*)(g_f2b + e0) = *(uint4*)o2;
}

// ---------------- K build: HMMA bf16 GEMM, cp.async double-buffered --------
// 128x128 block tile, 8 warps (2m x 4n), warp tile 64x32.
// K-chunks of 32 double-buffered via cp.async; __launch_bounds__(256,2)
// pins regs <= 128 so 2 blocks stay resident per SM.
#define KSTRIDE 136
__global__ __launch_bounds__(256, 2)
void fm_build_k(const float* __restrict__ pc1, const float* __restrict__ pc2) {
    __shared__ __nv_bfloat16 As[2][32][KSTRIDE];
    __shared__ __nv_bfloat16 Bs[2][32][KSTRIDE];
    __shared__ float sSq1[128], sSq2[128];
    __shared__ float sP1[3][128], sP2[3][128];

    int b  = blockIdx.z;
    int i0 = blockIdx.y * 128;
    int j0 = blockIdx.x * 128;
    int tid  = threadIdx.x;
    int warp = tid >> 5, lane = tid & 31;
    int wm = warp >> 2, wn = warp & 3;          // 2 x 4 warp grid

    if (tid < 128) {
        int i = i0 + tid;
        sSq1[tid] = g_sq1[b * NP + i];
#pragma unroll
        for (int d = 0; d < 3; d++)
            sP1[d][tid] = pc1[((size_t)b * 3 + d) * NP + i];
    } else {
        int t = tid - 128;
        int j = j0 + t;
        sSq2[t] = g_sq2[b * NP + j];
#pragma unroll
        for (int d = 0; d < 3; d++)
            sP2[d][t] = pc2[((size_t)b * 3 + d) * NP + j];
    }

    const __nv_bfloat16* F1 = g_f1b + (size_t)b * NC * NP;
    const __nv_bfloat16* F2 = g_f2b + (size_t)b * NC * NP;

    // async-load one 32-K chunk (A: 32x128, B: 32x128) into buffer buf
    auto load_chunk = [&](int c, int buf) {
#pragma unroll
        for (int k = 0; k < 2; k++) {
            int idx = tid + k * 256;             // 0..511
            int row = idx >> 4;                  // 16 uint4 per 128-col row
            int col = (idx & 15) * 8;
            uint32_t dA = (uint32_t)__cvta_generic_to_shared(&As[buf][row][col]);
            uint32_t dB = (uint32_t)__cvta_generic_to_shared(&Bs[buf][row][col]);
            const __nv_bfloat16* sA = F1 + (size_t)(c * 32 + row) * NP + i0 + col;
            const __nv_bfloat16* sB = F2 + (size_t)(c * 32 + row) * NP + j0 + col;
            asm volatile("cp.async.cg.shared.global [%0], [%1], 16;" :: "r"(dA), "l"(sA));
            asm volatile("cp.async.cg.shared.global [%0], [%1], 16;" :: "r"(dB), "l"(sB));
        }
        asm volatile("cp.async.commit_group;");
    };

    float acc[4][4][4];
#pragma unroll
    for (int fm = 0; fm < 4; fm++)
#pragma unroll
        for (int nb = 0; nb < 4; nb++)
#pragma unroll
            for (int e = 0; e < 4; e++) acc[fm][nb][e] = 0.f;

    int kA = ((lane >= 16) ? 8 : 0) + (lane & 7);   // A: k offset
    int mA = ((lane >> 3) & 1) * 8;                 // A: m offset
    int kB = (((lane >> 3) & 1) * 8) + (lane & 7);  // B: k offset
    int nB = (lane >= 16) ? 8 : 0;                  // B: n offset

    load_chunk(0, 0);

    const int NCHUNK = NC / 32;                      // 8
    for (int c = 0; c < NCHUNK; c++) {
        int buf = c & 1;
        if (c + 1 < NCHUNK) {
            load_chunk(c + 1, buf ^ 1);
            asm volatile("cp.async.wait_group 1;");  // chunk c landed
        } else {
            asm volatile("cp.async.wait_group 0;");
        }
        __syncthreads();
#pragma unroll
        for (int ks = 0; ks < 2; ks++) {
            int kb = ks * 16;
            uint32_t a[4][4];
#pragma unroll
            for (int fm = 0; fm < 4; fm++) {
                uint32_t saddr = (uint32_t)__cvta_generic_to_shared(
                    &As[buf][kb + kA][wm * 64 + fm * 16 + mA]);
                asm volatile("ldmatrix.sync.aligned.m8n8.x4.trans.shared.b16 "
                             "{%0,%1,%2,%3}, [%4];"
                             : "=r"(a[fm][0]), "=r"(a[fm][1]), "=r"(a[fm][2]), "=r"(a[fm][3])
                             : "r"(saddr));
            }
            uint32_t bb[2][4];
#pragma unroll
            for (int fn = 0; fn < 2; fn++) {
                uint32_t saddr = (uint32_t)__cvta_generic_to_shared(
                    &Bs[buf][kb + kB][wn * 32 + fn * 16 + nB]);
                asm volatile("ldmatrix.sync.aligned.m8n8.x4.trans.shared.b16 "
                             "{%0,%1,%2,%3}, [%4];"
                             : "=r"(bb[fn][0]), "=r"(bb[fn][1]), "=r"(bb[fn][2]), "=r"(bb[fn][3])
                             : "r"(saddr));
            }
#pragma unroll
            for (int fm = 0; fm < 4; fm++) {
#pragma unroll
                for (int nb = 0; nb < 4; nb++) {
                    int fn = nb >> 1, h = nb & 1;
                    asm volatile(
                        "mma.sync.aligned.m16n8k16.row.col.f32.bf16.bf16.f32 "
                        "{%0,%1,%2,%3}, {%4,%5,%6,%7}, {%8,%9}, {%0,%1,%2,%3};"
                        : "+f"(acc[fm][nb][0]), "+f"(acc[fm][nb][1]),
                          "+f"(acc[fm][nb][2]), "+f"(acc[fm][nb][3])
                        : "r"(a[fm][0]), "r"(a[fm][1]), "r"(a[fm][2]), "r"(a[fm][3]),
                          "r"(bb[fn][h * 2]), "r"(bb[fn][h * 2 + 1]));
                }
            }
        }
        __syncthreads();   // all reads of buf done before it is refilled
    }

    // epilogue: dist/support + exp, write bf16 pairs
    float einv = 1.0f / g_eps;
    int g  = lane >> 2;
    int t2 = (lane & 3) * 2;
    __nv_bfloat16* Kout = g_K + (size_t)b * NP * NP;
#pragma unroll
    for (int fm = 0; fm < 4; fm++) {
#pragma unroll
        for (int h = 0; h < 2; h++) {
            int ii = wm * 64 + fm * 16 + g + h * 8;
            float sq1 = sSq1[ii];
            float p1x = sP1[0][ii], p1y = sP1[1][ii], p1z = sP1[2][ii];
#pragma unroll
            for (int nb = 0; nb < 4; nb++) {
                int jj = wn * 32 + nb * 8 + t2;
                float c0 = acc[fm][nb][h * 2 + 0];
                float c1 = acc[fm][nb][h * 2 + 1];
                float d0 = sq1 + sSq2[jj]
                         - 2.0f * (p1x * sP2[0][jj] + p1y * sP2[1][jj] + p1z * sP2[2][jj]);
                float d1 = sq1 + sSq2[jj + 1]
                         - 2.0f * (p1x * sP2[0][jj + 1] + p1y * sP2[1][jj + 1] + p1z * sP2[2][jj + 1]);
                float k0 = (d0 < 0.25f) ? __expf((c0 - 1.0f) * einv) : 0.0f;
                float k1 = (d1 < 0.25f) ? __expf((c1 - 1.0f) * einv) : 0.0f;
                __nv_bfloat162 kv;
                kv.x = __float2bfloat16(k0);
                kv.y = __float2bfloat16(k1);
                *(__nv_bfloat162*)&Kout[(size_t)(i0 + ii) * NP + j0 + jj] = kv;
            }
        }
    }
}

// ---------------- Sinkhorn: KTa partials (column sweep, vectorized) --------
__global__ __launch_bounds__(256)
void fm_kta(void) {
    int b  = blockIdx.z;
    int j  = blockIdx.x * 2048 + threadIdx.x * 8;
    int i0 = blockIdx.y * (NP / ISPLIT);            // 32 rows per block
    const __nv_bfloat16* Kp = g_K + (size_t)b * NP * NP;
    const float* ap = g_a + b * NP;

    float acc[8];
#pragma unroll
    for (int k = 0; k < 8; k++) acc[k] = 0.f;

#pragma unroll 8
    for (int i = i0; i < i0 + NP / ISPLIT; i++) {
        uint4 kv = __ldg((const uint4*)(Kp + (size_t)i * NP + j));
        float av = __ldg(&ap[i]);
        float2 f0 = __bfloat1622float2(*(__nv_bfloat162*)&kv.x);
        float2 f1 = __bfloat1622float2(*(__nv_bfloat162*)&kv.y);
        float2 f2 = __bfloat1622float2(*(__nv_bfloat162*)&kv.z);
        float2 f3 = __bfloat1622float2(*(__nv_bfloat162*)&kv.w);
        acc[0] += f0.x * av; acc[1] += f0.y * av;
        acc[2] += f1.x * av; acc[3] += f1.y * av;
        acc[4] += f2.x * av; acc[5] += f2.y * av;
        acc[6] += f3.x * av; acc[7] += f3.y * av;
    }

    float* dst = &g_part[(size_t)blockIdx.y * (NB * NP) + b * NP + j];
    *(float4*)(dst + 0) = make_float4(acc[0], acc[1], acc[2], acc[3]);
    *(float4*)(dst + 4) = make_float4(acc[4], acc[5], acc[6], acc[7]);
}

// ---------------- b = (prob2/(sum partials + 1e-8))^power ------------------
__global__ __launch_bounds__(256)
void fm_b_update(void) {
    int t = blockIdx.x * blockDim.x + threadIdx.x;   // 0 .. 4*NB*NP-1
    int p = t >> 2;
    int q = t & 3;
    if (p >= NB * NP) return;
    float s = 0.f;
#pragma unroll
    for (int i = 0; i < ISPLIT / 4; i++) {
        int k = q * (ISPLIT / 4) + i;
        s += g_part[(size_t)k * (NB * NP) + p];
    }
    s += __shfl_xor_sync(0xffffffffu, s, 1);
    s += __shfl_xor_sync(0xffffffffu, s, 2);
    if (q == 0)
        g_b[p] = __powf((1.0f / NP) / (s + 1e-8f), g_power);
}

// ---------------- Kb (row sweep, vectorized) fused with a-update -----------
__global__ __launch_bounds__(256)
void fm_kb_a(void) {
    int warp = (blockIdx.x * blockDim.x + threadIdx.x) >> 5;
    int lane = threadIdx.x & 31;
    if (warp >= NB * NP) return;
    int b = warp >> 12, i = warp & (NP - 1);
    const __nv_bfloat16* Krow = g_K + (size_t)b * NP * NP + (size_t)i * NP;
    const float* bp = g_b + b * NP;
    float acc = 0.f;
#pragma unroll
    for (int it = 0; it < NP / 256; it++) {           // 16 iters
        int j = it * 256 + lane * 8;
        uint4 kv = __ldg((const uint4*)(Krow + j));
        float4 b0 = *(const float4*)(bp + j);
        float4 b1 = *(const float4*)(bp + j + 4);
        float2 f0 = __bfloat1622float2(*(__nv_bfloat162*)&kv.x);
        float2 f1 = __bfloat1622float2(*(__nv_bfloat162*)&kv.y);
        float2 f2 = __bfloat1622float2(*(__nv_bfloat162*)&kv.z);
        float2 f3 = __bfloat1622float2(*(__nv_bfloat162*)&kv.w);
        acc += f0.x * b0.x + f0.y * b0.y + f1.x * b0.z + f1.y * b0.w
             + f2.x * b1.x + f2.y * b1.y + f3.x * b1.z + f3.y * b1.w;
    }
#pragma unroll
    for (int o = 16; o; o >>= 1) acc += __shfl_xor_sync(0xffffffffu, acc, o);
    if (lane == 0)
        g_a[warp] = __powf((1.0f / NP) / (acc + 1e-8f), g_power);
}

// ---------------- last iteration: Kb + a-update + flow, one K pass ---------
__global__ __launch_bounds__(256)
void fm_kb_flow(const float* __restrict__ pc1, const float* __restrict__ pc2,
                float* __restrict__ out) {
    int warp = (blockIdx.x * blockDim.x + threadIdx.x) >> 5;
    int lane = threadIdx.x & 31;
    if (warp >= NB * NP) return;
    int b = warp >> 12, i = warp & (NP - 1);
    const __nv_bfloat16* Krow = g_K + (size_t)b * NP * NP + (size_t)i * NP;
    const float* bp  = g_b + b * NP;
    const float* p2x = pc2 + (size_t)b * 3 * NP;
    const float* p2y = p2x + NP;
    const float* p2z = p2y + NP;
    float s = 0.f, vx = 0.f, vy = 0.f, vz = 0.f;
#pragma unroll
    for (int it = 0; it < NP / 256; it++) {
        int j = it * 256 + lane * 8;
        uint4 kv = __ldg((const uint4*)(Krow + j));
        float2 f0 = __bfloat1622float2(*(__nv_bfloat162*)&kv.x);
        float2 f1 = __bfloat1622float2(*(__nv_bfloat162*)&kv.y);
        float2 f2 = __bfloat1622float2(*(__nv_bfloat162*)&kv.z);
        float2 f3 = __bfloat1622float2(*(__nv_bfloat162*)&kv.w);
        float4 b0 = *(const float4*)(bp + j);
        float4 b1 = *(const float4*)(bp + j + 4);
        float t[8];
        t[0] = f0.x * b0.x; t[1] = f0.y * b0.y; t[2] = f1.x * b0.z; t[3] = f1.y * b0.w;
        t[4] = f2.x * b1.x; t[5] = f2.y * b1.y; t[6] = f3.x * b1.z; t[7] = f3.y * b1.w;
        float4 x0 = *(const float4*)(p2x + j), x1 = *(const float4*)(p2x + j + 4);
        float4 y0 = *(const float4*)(p2y + j), y1 = *(const float4*)(p2y + j + 4);
        float4 z0 = *(const float4*)(p2z + j), z1 = *(const float4*)(p2z + j + 4);
        s  += t[0] + t[1] + t[2] + t[3] + t[4] + t[5] + t[6] + t[7];
        vx += t[0] * x0.x + t[1] * x0.y + t[2] * x0.z + t[3] * x0.w
            + t[4] * x1.x + t[5] * x1.y + t[6] * x1.z + t[7] * x1.w;
        vy += t[0] * y0.x + t[1] * y0.y + t[2] * y0.z + t[3] * y0.w
            + t[4] * y1.x + t[5] * y1.y + t[6] * y1.z + t[7] * y1.w;
        vz += t[0] * z0.x + t[1] * z0.y + t[2] * z0.z + t[3] * z0.w
            + t[4] * z1.x + t[5] * z1.y + t[6] * z1.z + t[7] * z1.w;
    }
#pragma unroll
    for (int o = 16; o; o >>= 1) {
        s  += __shfl_xor_sync(0xffffffffu, s,  o);
        vx += __shfl_xor_sync(0xffffffffu, vx, o);
        vy += __shfl_xor_sync(0xffffffffu, vy, o);
        vz += __shfl_xor_sync(0xffffffffu, vz, o);
    }
    if (lane == 0) {
        float a = __powf((1.0f / NP) / (s + 1e-8f), g_power);   // final a-update
        float rden = 1.0f / (a * s + 1e-6f);
        const float* P1 = pc1 + (size_t)b * 3 * NP + i;
        out[warp * 3 + 0] = a * vx * rden - P1[0 * NP];
        out[warp * 3 + 1] = a * vy * rden - P1[1 * NP];
        out[warp * 3 + 2] = a * vz * rden - P1[2 * NP];
    }
}

// ---------------- launch ----------------------------------------------------
extern "C" void kernel_launch(void* const* d_in, const int* in_sizes, int n_in,
                              void* d_out, int out_size) {
    const float* pc1   = (const float*)d_in[0];
    const float* pc2   = (const float*)d_in[1];
    const float* f1    = (const float*)d_in[2];
    const float* f2    = (const float*)d_in[3];
    const float* gamma = (const float*)d_in[4];
    const float* eps   = (const float*)d_in[5];
    float* out = (float*)d_out;

    fm_prep<<<1, 32>>>(gamma, eps);
    fm_point_prep<<<(NB * NP + 255) / 256, 256>>>(pc1, pc2, f1, f2);
    fm_convert<<<(NB * NC * NP / 8 + 255) / 256, 256>>>(f1, f2);
    fm_build_k<<<dim3(NP / 128, NP / 128, NB), 256>>>(pc1, pc2);

    // iteration 1: b1 from uniform a0
    fm_kta<<<dim3(NP / 2048, ISPLIT, NB), 256>>>();
    fm_b_update<<<(4 * NB * NP + 255) / 256, 256>>>();
    // iterations 1..9 (a_t then b_{t+1})
    for (int it = 0; it < 9; it++) {
        fm_kb_a<<<NB * NP / 8, 256>>>();
        fm_kta<<<dim3(NP / 2048, ISPLIT, NB), 256>>>();
        fm_b_update<<<(4 * NB * NP + 255) / 256, 256>>>();
    }
    // iteration 10: a10 = f(K b10) computed inside flow, fused with transport
    fm_kb_flow<<<NB * NP / 8, 256>>>(pc1, pc2, out);
}